// round 17
// baseline (speedup 1.0000x reference)
#include <cuda_runtime.h>
#include <cstdint>
#include <math.h>

#define NB      4
#define NGRID   512
#define NTARGET 1024
#define NBASIS  5
#define NCH     8

#define SPLIT   16                // grid chunks
#define CHUNK   (NGRID / SPLIT)   // 32 grid points per CTA
#define TILES   16                // 64-target tiles per batch
#define TPT     4                 // targets per thread
#define ROW2    (CHUNK + 2)       // float2 row stride (34) -> 16B-aligned rows

// Partial sums: [SPLIT][NB][NTARGET][NCH] = 2 MB, L2-resident
__device__ float d_part[SPLIT * NB * NTARGET * NCH];

__device__ __forceinline__ float ex2_mufu(float a) {
    float w;
    asm("ex2.approx.ftz.f32 %0, %1;" : "=f"(w) : "f"(a));
    return w;
}
// FMA-pipe exp2 for a <= 0 (rel err ~3e-5): ~7 fma-pipe + 2 alu ops.
__device__ __forceinline__ float ex2_poly(float a) {
    a = fmaxf(a, -126.0f);
    float r = a + 12582912.0f;            // 1.5*2^23 round-to-int trick
    float n = r - 12582912.0f;
    float f = a - n;                      // f in [-0.5, 0.5]
    float p = 0.0096181291f;
    p = fmaf(p, f, 0.0555041087f);
    p = fmaf(p, f, 0.2402265070f);
    p = fmaf(p, f, 0.6931471806f);
    p = fmaf(p, f, 1.0f);
    int ib = __float_as_int(r) << 23;     // == n << 23
    return __int_as_float(__float_as_int(p) + ib);
}

// ---------------------------------------------------------------------------
// Main kernel: 1024 CTAs x 128 threads (R15's winning shape — NO reg cap, so
// the hybrid exp cannot spill). CTA = (b, 64-target tile, 32-pt grid chunk).
// Warp = 2 channels x 16 target-lanes, TPT=4 -> 8 independent chains/thread.
// Math: exp2(-(xs-ts)^2) = exp2(2ts*xs - ts^2) * 2^(-xs^2), last factor folded
// into table h. Hybrid: 3 of 8 exps per iter on the FMA-pipe poly, 5 on MUFU.
// ---------------------------------------------------------------------------
__global__ void __launch_bounds__(128)
finallayer_part(const float* __restrict__ x_grid,    // [NB][NGRID][NCH]
                const float* __restrict__ h_grid,    // [NB][NGRID][NBASIS][NCH]
                const float* __restrict__ target_x,  // [NB][NTARGET][NCH]
                const float* __restrict__ sigma,     // [NBASIS][NCH]
                const float* __restrict__ g_w)       // [1][NBASIS]
{
    __shared__ __align__(16) float2 tbl[NCH * ROW2];  // (xs, h*2^-xs^2) ~2.2 KB
    __shared__ float s_part[64 * NCH];                // tile partials, 2 KB
    __shared__ float s_sc[NCH][NBASIS];
    __shared__ int   s_grp[NCH][NBASIS];
    __shared__ int   s_nu[NCH];
    __shared__ float s_gw[NBASIS];

    const int tid   = threadIdx.x;
    const int chunk = blockIdx.x & (SPLIT - 1);
    const int tile  = (blockIdx.x >> 4) & (TILES - 1);
    const int b     = blockIdx.x >> 8;          // bx = b*256 + tile*16 + chunk
    const int g0    = chunk * CHUNK;

    // --- per-channel scale dedup (redundant per CTA, trivial) ---
    if (tid < NCH) {
        const float C = 0.8493218002880190f;    // sqrt(0.5 * log2(e))
        float s[NBASIS], uniq[NBASIS];
        int nu = 0;
#pragma unroll
        for (int k = 0; k < NBASIS; ++k)
            s[k] = expf(sigma[k * NCH + tid]) + 1e-6f;
#pragma unroll
        for (int k = 0; k < NBASIS; ++k) {
            int u = -1;
            for (int j = 0; j < nu; ++j)
                if (uniq[j] == s[k]) { u = j; break; }
            if (u < 0) { u = nu; uniq[nu++] = s[k]; }
            s_grp[tid][k] = u;
        }
        s_nu[tid] = nu;
        for (int u = 0; u < nu; ++u) s_sc[tid][u] = C / uniq[u];
    } else if (tid < NCH + NBASIS) {
        s_gw[tid - NCH] = g_w[tid - NCH];
    }
    __syncthreads();

    // --- fill the 32-pt x 8-ch table (2 entries per thread) ---
    const float* xg = x_grid + (b * NGRID + g0) * NCH;
    const float* hg = h_grid + (b * NGRID + g0) * NBASIS * NCH;
    for (int i = tid; i < CHUNK * NCH; i += 128) {
        const int c = i & 7, g = i >> 3;
        float hv = 0.f;
#pragma unroll
        for (int k = 0; k < NBASIS; ++k)
            if (s_grp[c][k] == 0)
                hv += hg[(g * NBASIS + k) * NCH + c] * s_gw[k];
        float xs = xg[i] * s_sc[c][0];
        tbl[c * ROW2 + g] = make_float2(xs, hv * ex2_mufu(-xs * xs));
    }
    __syncthreads();

    // --- main loop: warp = 2 channels, lane 0-15 -> c0, 16-31 -> c1; TPT=4 ---
    const int lane = tid & 31;
    const int c    = ((tid >> 5) << 1) | (lane >> 4);
    const int tl   = lane & 15;
    const float sc0 = s_sc[c][0];

    float p2t[TPT], nt2[TPT], acc[TPT];
#pragma unroll
    for (int j = 0; j < TPT; ++j) {
        int t = tile * 64 + tl + 16 * j;
        float ts = __ldg(&target_x[(b * NTARGET + t) * NCH + c]) * sc0;
        p2t[j] = ts + ts;                       // 2*ts
        nt2[j] = -ts * ts;                      // -ts^2
        acc[j] = 0.f;
    }

    const float4* pc = (const float4*)(tbl + c * ROW2);  // broadcast LDS.128
#pragma unroll
    for (int gg = 0; gg < CHUNK / 2; ++gg) {
        float4 q = pc[gg];                      // (xs0, h0', xs1, h1')
#pragma unroll
        for (int j = 0; j < TPT; ++j) {
            float a0 = fmaf(q.x, p2t[j], nt2[j]);
            float a1 = fmaf(q.z, p2t[j], nt2[j]);
            // hybrid: 3 of 8 exponentials per iteration on the FMA pipe
            float w0 = (j <= 1) ? ex2_poly(a0) : ex2_mufu(a0);
            float w1 = (j == 0) ? ex2_poly(a1) : ex2_mufu(a1);
            acc[j] = fmaf(w0, q.y, acc[j]);
            acc[j] = fmaf(w1, q.w, acc[j]);
        }
    }

    // --- generic cold path: extra unique scales (not taken for uniform sigma) ---
    const int nu = s_nu[c];
    for (int u = 1; u < nu; ++u) {
        const float sc = s_sc[c][u];
        for (int g = 0; g < CHUNK; ++g) {
            float xv = __ldg(&xg[g * NCH + c]);
            float hv = 0.f;
#pragma unroll
            for (int k = 0; k < NBASIS; ++k)
                if (s_grp[c][k] == u)
                    hv += __ldg(&hg[(g * NBASIS + k) * NCH + c]) * s_gw[k];
            float xs = xv * sc;
#pragma unroll
            for (int j = 0; j < TPT; ++j) {
                int t = tile * 64 + tl + 16 * j;
                float ts = __ldg(&target_x[(b * NTARGET + t) * NCH + c]) * sc;
                float d  = xs - ts;
                acc[j] = fmaf(ex2_mufu(-d * d), hv, acc[j]);
            }
        }
    }

    // --- stage partials in smem, then fully-coalesced float4 store ---
#pragma unroll
    for (int j = 0; j < TPT; ++j)
        s_part[(tl + 16 * j) * NCH + c] = acc[j];
    __syncthreads();

    float4* dst = (float4*)(d_part +
        ((size_t)(chunk * NB + b) * NTARGET + tile * 64) * NCH);
    dst[tid] = ((const float4*)s_part)[tid];    // 512 floats = 128 float4
}

// ---------------------------------------------------------------------------
// Reduce (PDL secondary): float4 per thread, 16-deep MLP. Launch latency
// overlaps the main kernel via programmatic stream serialization.
// ---------------------------------------------------------------------------
__global__ void __launch_bounds__(128)
finallayer_red(const float* __restrict__ g_b, float* __restrict__ out)
{
    cudaGridDependencySynchronize();            // wait for main grid completion
    const int i = blockIdx.x * 128 + threadIdx.x;   // 0 .. 8191 (float4 index)
    const float4* p = (const float4*)d_part;
    const float bias = __ldg(g_b);
    float4 a = make_float4(bias, bias, bias, bias);
#pragma unroll
    for (int s = 0; s < SPLIT; ++s) {           // fixed order -> deterministic
        float4 v = p[(size_t)s * (NB * NTARGET * NCH / 4) + i];
        a.x += v.x; a.y += v.y; a.z += v.z; a.w += v.w;
    }
    ((float4*)out)[i] = a;
}

// ---------------------------------------------------------------------------
extern "C" void kernel_launch(void* const* d_in, const int* in_sizes, int n_in,
                              void* d_out, int out_size) {
    const float* x_grid   = (const float*)d_in[0];  // [4,512,8]
    const float* h_grid   = (const float*)d_in[1];  // [4,512,5,8]
    const float* target_x = (const float*)d_in[2];  // [4,1024,8]
    const float* sigma    = (const float*)d_in[3];  // [5,8]
    const float* g_w      = (const float*)d_in[4];  // [1,5]
    const float* g_b      = (const float*)d_in[5];  // [1]
    float* out = (float*)d_out;                     // [4,1024,8]

    finallayer_part<<<NB * TILES * SPLIT, 128>>>(
        x_grid, h_grid, target_x, sigma, g_w);

    cudaLaunchConfig_t cfg = {};
    cfg.gridDim  = dim3((NB * NTARGET * NCH / 4) / 128);  // 64 blocks
    cfg.blockDim = dim3(128);
    cudaLaunchAttribute attr[1];
    attr[0].id = cudaLaunchAttributeProgrammaticStreamSerialization;
    attr[0].val.programmaticStreamSerializationAllowed = 1;
    cfg.attrs = attr;
    cfg.numAttrs = 1;
    cudaLaunchKernelEx(&cfg, finallayer_red, g_b, out);
}